// round 15
// baseline (speedup 1.0000x reference)
#include <cuda_runtime.h>
#include <cuda_fp16.h>
#include <cstdint>

// ---------------------------------------------------------------------------
// Problem constants
// ---------------------------------------------------------------------------
static constexpr int KD = 4096;
static constexpr int ND = 4096;
static constexpr int MD = 4096;
static constexpr int NGROUPS = 32;       // K groups of 128

// GEMM tiling
static constexpr int BM = 128;
static constexpr int BN = 128;
static constexpr int BK = 32;
static constexpr int STAGES = 4;
static constexpr int NCHUNK = KD / BK;   // 128 ; scale group = 4 chunks
static constexpr int THREADS = 512;      // 16 warps

// SMEM stage layout (padded rows -> conflict-reduced ldmatrix phases)
static constexpr int A_ROWB = 80;              // 64B data + 16B pad
static constexpr int B_ROWB = 272;             // 256B data + 16B pad
static constexpr int SZ_A = BM * A_ROWB;       // 10240
static constexpr int SZ_B = BK * B_ROWB;       // 8704
static constexpr int OFF_A = 0;
static constexpr int OFF_B = SZ_A;
static constexpr int STAGE_BYTES = SZ_A + SZ_B;                // 18944
static constexpr int SC_BYTES = NGROUPS * BN * 4;              // 16384
static constexpr int SMEM_TOTAL = SC_BYTES + STAGES * STAGE_BYTES;  // 92160

// ---------------------------------------------------------------------------
// Scratch: A (x) fp16 [M,K]; B = (q - zp) exact small ints as fp16 [K,N]
// ---------------------------------------------------------------------------
__device__ __half g_Ax[(size_t)MD * KD];
__device__ __half g_Bd[(size_t)KD * ND];

// ---------------------------------------------------------------------------
// PTX helpers
// ---------------------------------------------------------------------------
__device__ __forceinline__ uint32_t smem_u32(const void* p) {
    uint32_t a;
    asm("{ .reg .u64 t; cvta.to.shared.u64 t, %1; cvt.u32.u64 %0, t; }" : "=r"(a) : "l"(p));
    return a;
}
__device__ __forceinline__ void cp_async16(uint32_t dst, const void* src) {
    asm volatile("cp.async.cg.shared.global [%0], [%1], 16;" :: "r"(dst), "l"(src));
}
__device__ __forceinline__ void cp_commit() {
    asm volatile("cp.async.commit_group;" ::: "memory");
}
__device__ __forceinline__ void ldsm4(uint32_t* r, uint32_t addr) {
    asm volatile("ldmatrix.sync.aligned.m8n8.x4.shared.b16 {%0,%1,%2,%3}, [%4];"
                 : "=r"(r[0]), "=r"(r[1]), "=r"(r[2]), "=r"(r[3]) : "r"(addr));
}
__device__ __forceinline__ void ldsm4t(uint32_t* r, uint32_t addr) {
    asm volatile("ldmatrix.sync.aligned.m8n8.x4.trans.shared.b16 {%0,%1,%2,%3}, [%4];"
                 : "=r"(r[0]), "=r"(r[1]), "=r"(r[2]), "=r"(r[3]) : "r"(addr));
}
// f16 accumulator variant: D(f16x2 pair) = A*B + C(f16x2 pair)
__device__ __forceinline__ void mma_f16acc(uint32_t* c, const uint32_t* a, const uint32_t* b) {
    asm volatile(
        "mma.sync.aligned.m16n8k16.row.col.f16.f16.f16.f16 "
        "{%0,%1}, {%2,%3,%4,%5}, {%6,%7}, {%0,%1};"
        : "+r"(c[0]), "+r"(c[1])
        : "r"(a[0]), "r"(a[1]), "r"(a[2]), "r"(a[3]), "r"(b[0]), "r"(b[1]));
}

// ---------------------------------------------------------------------------
// Prep 1: convert x (fp32 [M,K]) to fp16
// ---------------------------------------------------------------------------
__global__ __launch_bounds__(256) void conv_x_kernel(const float* __restrict__ x) {
    size_t i = (size_t)blockIdx.x * 256 + threadIdx.x;   // over M*K/4
    float4 v = reinterpret_cast<const float4*>(x)[i];
    __half2 p0 = __floats2half2_rn(v.x, v.y);
    __half2 p1 = __floats2half2_rn(v.z, v.w);
    reinterpret_cast<__half2*>(g_Ax)[i * 2 + 0] = p0;
    reinterpret_cast<__half2*>(g_Ax)[i * 2 + 1] = p1;
}

// ---------------------------------------------------------------------------
// Prep 2: d[k][n] = q[k][n] - zp[g(k)][n]  (small int, EXACT in fp16)
// ---------------------------------------------------------------------------
__global__ __launch_bounds__(256) void diff_kernel(
    const int* __restrict__ qw, const int* __restrict__ zp,
    const int* __restrict__ gidx) {
    size_t idx = (size_t)blockIdx.x * 256 + threadIdx.x;   // over K*N/4
    int n4 = (int)(idx & (ND / 4 - 1));
    int k  = (int)(idx >> 10);
    int g  = gidx[k];

    int4 q = reinterpret_cast<const int4*>(qw + (size_t)k * ND)[n4];
    int4 z = reinterpret_cast<const int4*>(zp + (size_t)g * ND)[n4];

    __half2 d0 = __floats2half2_rn((float)(q.x - z.x), (float)(q.y - z.y));
    __half2 d1 = __floats2half2_rn((float)(q.z - z.z), (float)(q.w - z.w));
    reinterpret_cast<__half2*>(g_Bd)[idx * 2 + 0] = d0;
    reinterpret_cast<__half2*>(g_Bd)[idx * 2 + 1] = d1;
}

// ---------------------------------------------------------------------------
// GEMM: C = x @ (sc * d) + bias ; scales factored out, f16 accum per chunk.
// 512 threads, 16 warps (4x4), warp tile 32x32.
// ---------------------------------------------------------------------------
__device__ __forceinline__ void load_stage(uint32_t sbase, int chunk,
                                           int m0, int n0, int t) {
    const int k0 = chunk * BK;
    // A tile: 128 rows x 4 segs of 16B = 512 segments
    {
        int row = t >> 2, seg = t & 3;
        uint32_t so = row * A_ROWB + seg * 16;
        size_t go = (size_t)(m0 + row) * KD + k0 + seg * 8;
        cp_async16(sbase + OFF_A + so, g_Ax + go);
    }
    // B tile: 32 rows x 16 segs of 16B = 512 segments
    {
        int row = t >> 4, seg = t & 15;
        uint32_t so = row * B_ROWB + seg * 16;
        size_t go = (size_t)(k0 + row) * ND + n0 + seg * 8;
        cp_async16(sbase + OFF_B + so, g_Bd + go);
    }
}

__global__ __launch_bounds__(THREADS, 1) void gemm_kernel(
    const float* __restrict__ scales,   // [NGROUPS, ND]
    const float* __restrict__ bias, float* __restrict__ C) {
    extern __shared__ char smem[];
    const uint32_t sb = smem_u32(smem);
    float* scs = reinterpret_cast<float*>(smem);          // [NGROUPS][BN]
    const uint32_t stage0 = sb + SC_BYTES;

    const int t = threadIdx.x;
    const int lane = t & 31;
    const int wid = t >> 5;            // 0..15
    const int wm = wid >> 2;           // 0..3  (32-row slice)
    const int wn = wid & 3;            // 0..3  (32-col slice)
    const int m0 = blockIdx.y * BM;
    const int n0 = blockIdx.x * BN;

    // Preload the 32x128 scale slab for this CTA's columns.
    #pragma unroll
    for (int u = 0; u < 2; u++) {
        int i = t + u * THREADS;           // 0..1023 float4s
        int g = i >> 5, j4 = i & 31;
        reinterpret_cast<float4*>(scs)[(size_t)g * 32 + j4] =
            *reinterpret_cast<const float4*>(scales + (size_t)g * ND + n0 + j4 * 4);
    }

    // ldmatrix per-thread base offsets
    const uint32_t a_off0 = (uint32_t)(wm * 32 + (lane & 15)) * A_ROWB + (lane >> 4) * 16;
    const uint32_t b_off0 = (uint32_t)(lane & 15) * B_ROWB + wn * 64 + (lane >> 4) * 16;

    float master[2][4][4];
    uint32_t part[2][4][2];            // f16x2 accumulators (chunk partials)
    #pragma unroll
    for (int f = 0; f < 2; f++)
        #pragma unroll
        for (int n = 0; n < 4; n++) {
            #pragma unroll
            for (int e = 0; e < 4; e++) master[f][n][e] = 0.0f;
            part[f][n][0] = 0u; part[f][n][1] = 0u;
        }

    // Prologue: stages 0..2
    load_stage(stage0 + 0 * STAGE_BYTES, 0, m0, n0, t);
    cp_commit();
    load_stage(stage0 + 1 * STAGE_BYTES, 1, m0, n0, t);
    cp_commit();
    load_stage(stage0 + 2 * STAGE_BYTES, 2, m0, n0, t);
    cp_commit();

    const int col0 = (lane & 3) * 2;

    #pragma unroll 1
    for (int c = 0; c < NCHUNK; c++) {
        const int slot = c & 3;
        asm volatile("cp.async.wait_group 2;" ::: "memory");
        __syncthreads();

        // Prefetch one REAL group every iteration (dup reload of last chunk in
        // the tail keeps wait_group depth accounting exact).
        {
            int pc = (c + 3 < NCHUNK) ? (c + 3) : (NCHUNK - 1);
            load_stage(stage0 + ((c + 3) & 3) * STAGE_BYTES, pc, m0, n0, t);
            cp_commit();
        }

        const uint32_t stage = stage0 + slot * STAGE_BYTES;

        #pragma unroll
        for (int ks = 0; ks < 2; ks++) {
            uint32_t Af[2][4], Bd[4][2];
            #pragma unroll
            for (int f = 0; f < 2; f++) {
                uint32_t ao = a_off0 + f * 16 * A_ROWB + ks * 32;
                ldsm4(Af[f], stage + OFF_A + ao);
            }
            #pragma unroll
            for (int p = 0; p < 2; p++) {
                uint32_t bo = b_off0 + ks * 16 * B_ROWB + p * 32;
                uint32_t tmp[4];
                ldsm4t(tmp, stage + OFF_B + bo);
                Bd[2 * p][0] = tmp[0]; Bd[2 * p][1] = tmp[1];
                Bd[2 * p + 1][0] = tmp[2]; Bd[2 * p + 1][1] = tmp[3];
            }
            #pragma unroll
            for (int f = 0; f < 2; f++)
                #pragma unroll
                for (int n = 0; n < 4; n++)
                    mma_f16acc(part[f][n], Af[f], Bd[n]);
        }

        // Fold chunk partial into fp32 master with group scale (f16 accums
        // only ever hold a K=32 partial -> bounded rounding error).
        {
            const int g = c >> 2;
            #pragma unroll
            for (int n = 0; n < 4; n++) {
                const float2 s2 = *reinterpret_cast<const float2*>(
                    scs + (size_t)g * BN + wn * 32 + n * 8 + col0);
                #pragma unroll
                for (int f = 0; f < 2; f++) {
                    float2 lo = __half22float2(
                        *reinterpret_cast<__half2*>(&part[f][n][0]));
                    float2 hi = __half22float2(
                        *reinterpret_cast<__half2*>(&part[f][n][1]));
                    master[f][n][0] += s2.x * lo.x;
                    master[f][n][1] += s2.y * lo.y;
                    master[f][n][2] += s2.x * hi.x;
                    master[f][n][3] += s2.y * hi.y;
                    part[f][n][0] = 0u; part[f][n][1] = 0u;
                }
            }
        }
    }

    // Epilogue: bias + store
    const int row0 = lane >> 2;
    #pragma unroll
    for (int n = 0; n < 4; n++) {
        const int gc = n0 + wn * 32 + n * 8 + col0;
        const float2 bb = *reinterpret_cast<const float2*>(bias + gc);
        #pragma unroll
        for (int f = 0; f < 2; f++) {
            const int gr = m0 + wm * 32 + f * 16 + row0;
            float2 o0, o1;
            o0.x = master[f][n][0] + bb.x;
            o0.y = master[f][n][1] + bb.y;
            o1.x = master[f][n][2] + bb.x;
            o1.y = master[f][n][3] + bb.y;
            *reinterpret_cast<float2*>(C + (size_t)gr * ND + gc) = o0;
            *reinterpret_cast<float2*>(C + (size_t)(gr + 8) * ND + gc) = o1;
        }
    }
}

// ---------------------------------------------------------------------------
// Launch. Inputs: x, qweight_int, scales, zero_points, g_idx, bias. Out: fp32.
// ---------------------------------------------------------------------------
extern "C" void kernel_launch(void* const* d_in, const int* in_sizes, int n_in,
                              void* d_out, int out_size) {
    const float* x    = (const float*)d_in[0];
    const int*   qw   = (const int*)  d_in[1];
    const float* sc   = (const float*)d_in[2];
    const int*   zp   = (const int*)  d_in[3];
    const int*   gidx = (const int*)  d_in[4];
    const float* bias = (const float*)d_in[5];
    float*       out  = (float*)d_out;

    const int M = in_sizes[0] / KD;   // 4096

    cudaFuncSetAttribute(gemm_kernel,
                         cudaFuncAttributeMaxDynamicSharedMemorySize, SMEM_TOTAL);

    conv_x_kernel<<<(M * KD / 4) / 256, 256>>>(x);
    diff_kernel<<<(KD * (ND / 4)) / 256, 256>>>(qw, zp, gidx);
    gemm_kernel<<<dim3(ND / BN, M / BM), THREADS, SMEM_TOTAL>>>(sc, bias, out);
}

// round 17
// speedup vs baseline: 1.3221x; 1.3221x over previous
#include <cuda_runtime.h>
#include <cuda_fp16.h>
#include <cstdint>

// ---------------------------------------------------------------------------
// Problem constants
// ---------------------------------------------------------------------------
static constexpr int KD = 4096;
static constexpr int ND = 4096;
static constexpr int MD = 4096;
static constexpr int NGROUPS = 32;       // K groups of 128

// GEMM tiling
static constexpr int BM = 128;
static constexpr int BN = 128;
static constexpr int BK = 64;
static constexpr int STAGES = 3;
static constexpr int NCHUNK = KD / BK;   // 64 ; scale group = 2 chunks
static constexpr int THREADS = 512;      // 16 warps

// SMEM stage layout (padded rows -> conflict-reduced ldmatrix phases)
static constexpr int A_ROWB = 144;             // 128B data + 16B pad
static constexpr int B_ROWB = 272;             // 256B data + 16B pad
static constexpr int SZ_A = BM * A_ROWB;       // 18432
static constexpr int SZ_B = BK * B_ROWB;       // 17408
static constexpr int OFF_A = 0;
static constexpr int OFF_B = SZ_A;
static constexpr int STAGE_BYTES = SZ_A + SZ_B;                // 35840
static constexpr int SC_BYTES = NGROUPS * BN * 4;              // 16384
static constexpr int SMEM_TOTAL = SC_BYTES + STAGES * STAGE_BYTES;  // 123904

// ---------------------------------------------------------------------------
// Scratch: A (x) fp16 [M,K]; B = (q - zp) exact small ints as fp16 [K,N]
// ---------------------------------------------------------------------------
__device__ __half g_Ax[(size_t)MD * KD];
__device__ __half g_Bd[(size_t)KD * ND];

// ---------------------------------------------------------------------------
// PTX helpers
// ---------------------------------------------------------------------------
__device__ __forceinline__ uint32_t smem_u32(const void* p) {
    uint32_t a;
    asm("{ .reg .u64 t; cvta.to.shared.u64 t, %1; cvt.u32.u64 %0, t; }" : "=r"(a) : "l"(p));
    return a;
}
__device__ __forceinline__ void cp_async16(uint32_t dst, const void* src) {
    asm volatile("cp.async.cg.shared.global [%0], [%1], 16;" :: "r"(dst), "l"(src));
}
__device__ __forceinline__ void cp_commit() {
    asm volatile("cp.async.commit_group;" ::: "memory");
}
__device__ __forceinline__ void ldsm4(uint32_t* r, uint32_t addr) {
    asm volatile("ldmatrix.sync.aligned.m8n8.x4.shared.b16 {%0,%1,%2,%3}, [%4];"
                 : "=r"(r[0]), "=r"(r[1]), "=r"(r[2]), "=r"(r[3]) : "r"(addr));
}
__device__ __forceinline__ void ldsm4t(uint32_t* r, uint32_t addr) {
    asm volatile("ldmatrix.sync.aligned.m8n8.x4.trans.shared.b16 {%0,%1,%2,%3}, [%4];"
                 : "=r"(r[0]), "=r"(r[1]), "=r"(r[2]), "=r"(r[3]) : "r"(addr));
}
__device__ __forceinline__ void mma_f16(float* c, const uint32_t* a, const uint32_t* b) {
    asm volatile(
        "mma.sync.aligned.m16n8k16.row.col.f32.f16.f16.f32 "
        "{%0,%1,%2,%3}, {%4,%5,%6,%7}, {%8,%9}, {%0,%1,%2,%3};"
        : "+f"(c[0]), "+f"(c[1]), "+f"(c[2]), "+f"(c[3])
        : "r"(a[0]), "r"(a[1]), "r"(a[2]), "r"(a[3]), "r"(b[0]), "r"(b[1]));
}

// ---------------------------------------------------------------------------
// Fused prep: blocks [0, MK4) convert x to fp16; blocks [MK4, MK4+KN4) build
// d = q - zp (exact small ints in fp16). Single launch -> DRAM streams overlap.
// ---------------------------------------------------------------------------
static constexpr int PREP_XBLOCKS = (MD * (KD / 4)) / 256;   // 16384
static constexpr int PREP_BBLOCKS = (KD * (ND / 4)) / 256;   //  4096

__global__ __launch_bounds__(256) void prep_kernel(
    const float* __restrict__ x,
    const int* __restrict__ qw, const int* __restrict__ zp,
    const int* __restrict__ gidx) {
    if (blockIdx.x < PREP_XBLOCKS) {
        size_t i = (size_t)blockIdx.x * 256 + threadIdx.x;   // over M*K/4
        float4 v = reinterpret_cast<const float4*>(x)[i];
        reinterpret_cast<__half2*>(g_Ax)[i * 2 + 0] = __floats2half2_rn(v.x, v.y);
        reinterpret_cast<__half2*>(g_Ax)[i * 2 + 1] = __floats2half2_rn(v.z, v.w);
    } else {
        size_t idx = (size_t)(blockIdx.x - PREP_XBLOCKS) * 256 + threadIdx.x;
        int n4 = (int)(idx & (ND / 4 - 1));
        int k  = (int)(idx >> 10);
        int g  = gidx[k];
        int4 q = reinterpret_cast<const int4*>(qw + (size_t)k * ND)[n4];
        int4 z = reinterpret_cast<const int4*>(zp + (size_t)g * ND)[n4];
        reinterpret_cast<__half2*>(g_Bd)[idx * 2 + 0] =
            __floats2half2_rn((float)(q.x - z.x), (float)(q.y - z.y));
        reinterpret_cast<__half2*>(g_Bd)[idx * 2 + 1] =
            __floats2half2_rn((float)(q.z - z.z), (float)(q.w - z.w));
    }
}

// ---------------------------------------------------------------------------
// GEMM: C = x @ (sc * d) + bias ; scales factored out per K-group.
// 512 threads, 16 warps (4x4), warp tile 32x32, BK=64 per stage.
// ---------------------------------------------------------------------------
__device__ __forceinline__ void load_stage(uint32_t sbase, int chunk,
                                           int m0, int n0, int t) {
    const int k0 = chunk * BK;
    // A tile: 128 rows x 8 segs of 16B = 1024 segments
    #pragma unroll
    for (int u = 0; u < 2; u++) {
        int idx = t + u * THREADS;        // 0..1023
        int row = idx >> 3, seg = idx & 7;
        uint32_t so = row * A_ROWB + seg * 16;
        size_t go = (size_t)(m0 + row) * KD + k0 + seg * 8;
        cp_async16(sbase + OFF_A + so, g_Ax + go);
    }
    // B tile: 64 rows x 16 segs of 16B = 1024 segments
    #pragma unroll
    for (int u = 0; u < 2; u++) {
        int idx = t + u * THREADS;        // 0..1023
        int row = idx >> 4, seg = idx & 15;
        uint32_t so = row * B_ROWB + seg * 16;
        size_t go = (size_t)(k0 + row) * ND + n0 + seg * 8;
        cp_async16(sbase + OFF_B + so, g_Bd + go);
    }
}

__global__ __launch_bounds__(THREADS, 1) void gemm_kernel(
    const float* __restrict__ scales,   // [NGROUPS, ND]
    const float* __restrict__ bias, float* __restrict__ C) {
    extern __shared__ char smem[];
    const uint32_t sb = smem_u32(smem);
    float* scs = reinterpret_cast<float*>(smem);          // [NGROUPS][BN]
    const uint32_t stage0 = sb + SC_BYTES;

    const int t = threadIdx.x;
    const int lane = t & 31;
    const int wid = t >> 5;            // 0..15
    const int wm = wid >> 2;           // 0..3  (32-row slice)
    const int wn = wid & 3;            // 0..3  (32-col slice)
    const int m0 = blockIdx.y * BM;
    const int n0 = blockIdx.x * BN;

    // Preload the 32x128 scale slab for this CTA's columns.
    #pragma unroll
    for (int u = 0; u < 2; u++) {
        int i = t + u * THREADS;           // 0..1023 float4s
        int g = i >> 5, j4 = i & 31;
        reinterpret_cast<float4*>(scs)[(size_t)g * 32 + j4] =
            *reinterpret_cast<const float4*>(scales + (size_t)g * ND + n0 + j4 * 4);
    }

    // ldmatrix per-thread base offsets
    const uint32_t a_off0 = (uint32_t)(wm * 32 + (lane & 15)) * A_ROWB + (lane >> 4) * 16;
    const uint32_t b_off0 = (uint32_t)(lane & 15) * B_ROWB + wn * 64 + (lane >> 4) * 16;

    float master[2][4][4];
    float part[2][4][4];
    #pragma unroll
    for (int f = 0; f < 2; f++)
        #pragma unroll
        for (int n = 0; n < 4; n++)
            #pragma unroll
            for (int e = 0; e < 4; e++) {
                master[f][n][e] = 0.0f;
                part[f][n][e] = 0.0f;
            }

    // Prologue: stages 0, 1
    load_stage(stage0 + 0 * STAGE_BYTES, 0, m0, n0, t);
    cp_commit();
    load_stage(stage0 + 1 * STAGE_BYTES, 1, m0, n0, t);
    cp_commit();

    const int col0 = (lane & 3) * 2;

    int slot = 0;
    #pragma unroll 1
    for (int c = 0; c < NCHUNK; c++) {
        asm volatile("cp.async.wait_group 1;" ::: "memory");
        __syncthreads();

        // Prefetch one REAL group every iteration (dup reload of last chunk in
        // the tail keeps wait_group depth accounting exact).
        {
            int pc = (c + 2 < NCHUNK) ? (c + 2) : (NCHUNK - 1);
            int ns = slot + 2; if (ns >= STAGES) ns -= STAGES;
            load_stage(stage0 + ns * STAGE_BYTES, pc, m0, n0, t);
            cp_commit();
        }

        const uint32_t stage = stage0 + slot * STAGE_BYTES;

        #pragma unroll
        for (int ks = 0; ks < 4; ks++) {
            uint32_t Af[2][4], Bd[4][2];
            #pragma unroll
            for (int f = 0; f < 2; f++) {
                uint32_t ao = a_off0 + f * 16 * A_ROWB + ks * 32;
                ldsm4(Af[f], stage + OFF_A + ao);
            }
            #pragma unroll
            for (int p = 0; p < 2; p++) {
                uint32_t bo = b_off0 + ks * 16 * B_ROWB + p * 32;
                uint32_t tmp[4];
                ldsm4t(tmp, stage + OFF_B + bo);
                Bd[2 * p][0] = tmp[0]; Bd[2 * p][1] = tmp[1];
                Bd[2 * p + 1][0] = tmp[2]; Bd[2 * p + 1][1] = tmp[3];
            }
            #pragma unroll
            for (int f = 0; f < 2; f++)
                #pragma unroll
                for (int n = 0; n < 4; n++)
                    mma_f16(part[f][n], Af[f], Bd[n]);
        }

        // End of a K-group (2 chunks of 64): fold scaled partials into master.
        if (c & 1) {
            const int g = c >> 1;
            #pragma unroll
            for (int n = 0; n < 4; n++) {
                const float2 s2 = *reinterpret_cast<const float2*>(
                    scs + (size_t)g * BN + wn * 32 + n * 8 + col0);
                #pragma unroll
                for (int f = 0; f < 2; f++) {
                    master[f][n][0] += s2.x * part[f][n][0];
                    master[f][n][1] += s2.y * part[f][n][1];
                    master[f][n][2] += s2.x * part[f][n][2];
                    master[f][n][3] += s2.y * part[f][n][3];
                    part[f][n][0] = 0.0f; part[f][n][1] = 0.0f;
                    part[f][n][2] = 0.0f; part[f][n][3] = 0.0f;
                }
            }
        }

        slot++; if (slot >= STAGES) slot = 0;
    }

    // Epilogue: bias + store
    const int row0 = lane >> 2;
    #pragma unroll
    for (int n = 0; n < 4; n++) {
        const int gc = n0 + wn * 32 + n * 8 + col0;
        const float2 bb = *reinterpret_cast<const float2*>(bias + gc);
        #pragma unroll
        for (int f = 0; f < 2; f++) {
            const int gr = m0 + wm * 32 + f * 16 + row0;
            float2 o0, o1;
            o0.x = master[f][n][0] + bb.x;
            o0.y = master[f][n][1] + bb.y;
            o1.x = master[f][n][2] + bb.x;
            o1.y = master[f][n][3] + bb.y;
            *reinterpret_cast<float2*>(C + (size_t)gr * ND + gc) = o0;
            *reinterpret_cast<float2*>(C + (size_t)(gr + 8) * ND + gc) = o1;
        }
    }
}

// ---------------------------------------------------------------------------
// Launch. Inputs: x, qweight_int, scales, zero_points, g_idx, bias. Out: fp32.
// ---------------------------------------------------------------------------
extern "C" void kernel_launch(void* const* d_in, const int* in_sizes, int n_in,
                              void* d_out, int out_size) {
    const float* x    = (const float*)d_in[0];
    const int*   qw   = (const int*)  d_in[1];
    const float* sc   = (const float*)d_in[2];
    const int*   zp   = (const int*)  d_in[3];
    const int*   gidx = (const int*)  d_in[4];
    const float* bias = (const float*)d_in[5];
    float*       out  = (float*)d_out;

    cudaFuncSetAttribute(gemm_kernel,
                         cudaFuncAttributeMaxDynamicSharedMemorySize, SMEM_TOTAL);

    prep_kernel<<<PREP_XBLOCKS + PREP_BBLOCKS, 256>>>(x, qw, zp, gidx);
    gemm_kernel<<<dim3(ND / BN, MD / BM), THREADS, SMEM_TOTAL>>>(sc, bias, out);
}